// round 14
// baseline (speedup 1.0000x reference)
#include <cuda_runtime.h>
#include <cuda_bf16.h>
#include <cstdint>
#include <cstddef>

// Problem constants
#define BB    4096
#define TT    32
#define HH    16
#define HSD   32
#define EE    512
#define QKVC  1536
#define MROWS (BB * TT)    // 131072
#define WROWS 2048         // 1536 qkv rows + 512 proj rows

// ---------------------------------------------------------------------------
// Scratch (__device__ globals; no allocation anywhere).  NOTE: g_qkv is gone —
// attention is fused into the QKV GEMM epilogue (the fp32 qkv round-trip was
// ~950us of the R13 runtime).
// ---------------------------------------------------------------------------
__device__ unsigned short g_xhi[(size_t)MROWS * EE];
__device__ unsigned short g_xlo[(size_t)MROWS * EE];
__device__ unsigned short g_whi[(size_t)WROWS * EE];  // rows: 0-511 Wq, 512-1023 Wk, 1024-1535 Wv, 1536-2047 Wp
__device__ unsigned short g_wlo[(size_t)WROWS * EE];
__device__ unsigned short g_ohi[(size_t)MROWS * EE];  // attn out, row=b*32+d, col=h*32+t
__device__ unsigned short g_olo[(size_t)MROWS * EE];

__device__ __forceinline__ void split_bf16(float v, unsigned short& hi, unsigned short& lo) {
    __nv_bfloat16 h = __float2bfloat16_rn(v);
    float r = v - __bfloat162float(h);
    __nv_bfloat16 l = __float2bfloat16_rn(r);
    hi = __bfloat16_as_ushort(h);
    lo = __bfloat16_as_ushort(l);
}

// ---------------------------------------------------------------------------
// Merged conversion kernel (one launch): blocks [0, 65536) split x,
// blocks [65536, 66560) split the four weight matrices.
// ---------------------------------------------------------------------------
#define CONV_X_BLOCKS (MROWS * EE / 1024)   // 65536
#define CONV_W_BLOCKS (WROWS * EE / 1024)   // 1024

__global__ __launch_bounds__(256) void k_conv(const float* __restrict__ x,
                                              const float* __restrict__ Wq,
                                              const float* __restrict__ Wk,
                                              const float* __restrict__ Wv,
                                              const float* __restrict__ Wp) {
    const int bid = blockIdx.x;
    unsigned short h0,h1,h2,h3,l0,l1,l2,l3;
    if (bid < CONV_X_BLOCKS) {
        size_t i = ((size_t)bid * 256 + threadIdx.x) * 4;
        float4 v = __ldcs((const float4*)(x + i));
        split_bf16(v.x,h0,l0); split_bf16(v.y,h1,l1);
        split_bf16(v.z,h2,l2); split_bf16(v.w,h3,l3);
        *(uint2*)(g_xhi + i) = make_uint2((unsigned)h0 | ((unsigned)h1 << 16),
                                          (unsigned)h2 | ((unsigned)h3 << 16));
        *(uint2*)(g_xlo + i) = make_uint2((unsigned)l0 | ((unsigned)l1 << 16),
                                          (unsigned)l2 | ((unsigned)l3 << 16));
    } else {
        size_t i = ((size_t)(bid - CONV_X_BLOCKS) * 256 + threadIdx.x) * 4;  // over 2048*512
        int region = (int)(i >> 18);    // 0=Wq 1=Wk 2=Wv 3=Wp
        const float* src = (region == 0) ? Wq : (region == 1) ? Wk : (region == 2) ? Wv : Wp;
        float4 v = *(const float4*)(src + (i - ((size_t)region << 18)));
        split_bf16(v.x,h0,l0); split_bf16(v.y,h1,l1);
        split_bf16(v.z,h2,l2); split_bf16(v.w,h3,l3);
        *(uint2*)(g_whi + i) = make_uint2((unsigned)h0 | ((unsigned)h1 << 16),
                                          (unsigned)h2 | ((unsigned)h3 << 16));
        *(uint2*)(g_wlo + i) = make_uint2((unsigned)l0 | ((unsigned)l1 << 16),
                                          (unsigned)l2 | ((unsigned)l3 << 16));
    }
}

// ---------------------------------------------------------------------------
// PTX helpers (sm_103-safe)
// ---------------------------------------------------------------------------
__device__ __forceinline__ void mma16816(float* d, const uint32_t* a, uint32_t b0, uint32_t b1) {
    asm volatile(
        "mma.sync.aligned.m16n8k16.row.col.f32.bf16.bf16.f32 "
        "{%0,%1,%2,%3}, {%4,%5,%6,%7}, {%8,%9}, {%0,%1,%2,%3};"
        : "+f"(d[0]), "+f"(d[1]), "+f"(d[2]), "+f"(d[3])
        : "r"(a[0]), "r"(a[1]), "r"(a[2]), "r"(a[3]), "r"(b0), "r"(b1));
}
__device__ __forceinline__ void ldsm_x4(uint32_t* r, uint32_t addr) {
    asm volatile("ldmatrix.sync.aligned.m8n8.x4.shared.b16 {%0,%1,%2,%3}, [%4];"
                 : "=r"(r[0]), "=r"(r[1]), "=r"(r[2]), "=r"(r[3]) : "r"(addr));
}
__device__ __forceinline__ void cp16(uint32_t saddr, const void* gaddr) {
    asm volatile("cp.async.cg.shared.global [%0], [%1], 16;" :: "r"(saddr), "l"(gaddr));
}
__device__ __forceinline__ void cp_commit() { asm volatile("cp.async.commit_group;" ::: "memory"); }
__device__ __forceinline__ void cp_wait0()  { asm volatile("cp.async.wait_group 0;" ::: "memory"); }
__device__ __forceinline__ void cp_wait1()  { asm volatile("cp.async.wait_group 1;" ::: "memory"); }

// ===========================================================================
// Kernel 1: FUSED QKV-GEMM + attention.
// Grid (16 heads, 1024 m-blocks).  CTA tile: M=128 rows (4 complete batches)
// x N=96 cols = head h's {q(32) | k(32) | v(32)} channels.
// Mainloop = the validated 3-MMA bf16-split pipeline (BK=32, 3-stage
// cp.async, conflict-free swizzle), warp tile 32x48 (8 warps, 4m x 2n).
// Epilogue: acc -> smem (stride 97: conflict-free), then the validated
// shuffle-softmax attention per batch, bf16 hi/lo output only.
// B smem rows r (0..95) map to weight rows (r/32)*512 + h*32 + (r%32).
// Stage: Ahi@0(8K) Alo@8K Bhi@16K(6K) Blo@22K(6K) = 28KB; 3 stages = 84KB.
// sqkv (128x97 fp32 = 49.7KB) reuses stage area post-mainloop; so = +4.2KB.
// ===========================================================================
#define FQ_STAGE_BYTES 28672
#define FQ_SO_OFF      (3 * FQ_STAGE_BYTES)               // 86016
#define FQ_SMEM_BYTES  (FQ_SO_OFF + 32 * 33 * 4)          // 90240, 2 CTAs/SM

__global__ __launch_bounds__(256, 2) void k_qkv_attn(
    const unsigned short* __restrict__ Ahi, const unsigned short* __restrict__ Alo) {

    extern __shared__ unsigned short sm[];
    const uint32_t uSm = (uint32_t)__cvta_generic_to_shared(sm);

    const int tid  = threadIdx.x;
    const int wid  = tid >> 5;
    const int lane = tid & 31;
    const int h    = blockIdx.x;          // head
    const int m0   = blockIdx.y * 128;    // 4 batches: blockIdx.y*4 ..
    const int wm   = (wid >> 1) * 32;
    const int wn   = (wid & 1) * 48;

    float acc[2][6][4];
#pragma unroll
    for (int mt = 0; mt < 2; mt++)
#pragma unroll
        for (int nt = 0; nt < 6; nt++)
#pragma unroll
            for (int e = 0; e < 4; e++) acc[mt][nt][e] = 0.0f;

    const int NSTEP = EE / 32;   // 16

    auto load_stage = [&](int s, int k0) {
        const uint32_t sb = uSm + (uint32_t)s * FQ_STAGE_BYTES;
        // A: 128 rows x 4 chunks = 512 chunk-ids, 2 per thread
#pragma unroll
        for (int p = 0; p < 2; p++) {
            const int id = tid + p * 256;
            const int r = id >> 2, c = id & 3;
            const uint32_t so = (uint32_t)(r * 32 + ((c ^ ((r >> 1) & 3)) << 3)) * 2u;
            const size_t aof = (size_t)(m0 + r) * EE + k0 + c * 8;
            cp16(sb +         so, Ahi + aof);
            cp16(sb + 8192u + so, Alo + aof);
        }
        // B: 96 rows x 4 chunks = 384 chunk-ids; row r -> weight row
        // (r/32)*512 + h*32 + (r%32)  (q / k / v section of this head)
#pragma unroll
        for (int p = 0; p < 2; p++) {
            const int id = tid + p * 256;
            if (id < 384) {
                const int r = id >> 2, c = id & 3;
                const int grow = (r >> 5) * 512 + h * 32 + (r & 31);
                const uint32_t so = (uint32_t)(r * 32 + ((c ^ ((r >> 1) & 3)) << 3)) * 2u;
                const size_t bof = (size_t)grow * EE + k0 + c * 8;
                cp16(sb + 16384u + so, g_whi + bof);
                cp16(sb + 22528u + so, g_wlo + bof);
            }
        }
    };

    const int q  = lane >> 3;     // ldmatrix quadrant
    const int ri = lane & 7;

    load_stage(0, 0);  cp_commit();
    load_stage(1, 32); cp_commit();

    int cur = 0;
#pragma unroll 1
    for (int kt = 0; kt < NSTEP; kt++) {
        if (kt < NSTEP - 2) cp_wait1(); else cp_wait0();
        __syncthreads();
        if (kt + 2 < NSTEP) {
            load_stage((cur + 2) % 3, (kt + 2) * 32);
            cp_commit();
        }

        const uint32_t sb   = uSm + (uint32_t)cur * FQ_STAGE_BYTES;
        const uint32_t bAhi = sb,          bAlo = sb + 8192u;
        const uint32_t bBhi = sb + 16384u, bBlo = sb + 22528u;

#pragma unroll
        for (int s = 0; s < 2; s++) {
            uint32_t afr[2][2][4];
#pragma unroll
            for (int mt = 0; mt < 2; mt++) {
                const int r = wm + mt * 16 + (q & 1) * 8 + ri;
                const int j = 2 * s + (q >> 1);
                const uint32_t off = (uint32_t)(r * 32 + ((j ^ ((r >> 1) & 3)) << 3)) * 2u;
                ldsm_x4(afr[mt][0], bAhi + off);
                ldsm_x4(afr[mt][1], bAlo + off);
            }
#pragma unroll
            for (int np = 0; np < 3; np++) {     // 3 pairs of n8 tiles (48 cols)
                const int r = wn + np * 16 + (q >> 1) * 8 + ri;
                const int j = 2 * s + (q & 1);
                const uint32_t off = (uint32_t)(r * 32 + ((j ^ ((r >> 1) & 3)) << 3)) * 2u;
                uint32_t bh[4], bl[4];
                ldsm_x4(bh, bBhi + off);
                ldsm_x4(bl, bBlo + off);
#pragma unroll
                for (int mt = 0; mt < 2; mt++) {
                    float* d0 = acc[mt][2 * np];
                    float* d1 = acc[mt][2 * np + 1];
                    mma16816(d0, afr[mt][0], bh[0], bh[1]);   // hi*hi
                    mma16816(d0, afr[mt][0], bl[0], bl[1]);   // hi*lo
                    mma16816(d0, afr[mt][1], bh[0], bh[1]);   // lo*hi
                    mma16816(d1, afr[mt][0], bh[2], bh[3]);
                    mma16816(d1, afr[mt][0], bl[2], bl[3]);
                    mma16816(d1, afr[mt][1], bh[2], bh[3]);
                }
            }
        }
        cur = (cur + 1) % 3;
    }

    // ---- Fused attention epilogue ----
    __syncthreads();                       // all warps out of the mainloop smem
    float* sqkv = (float*)sm;              // [128][97]: cols 0-31 q, 32-63 k, 64-95 v
    float* so   = (float*)((char*)sm + FQ_SO_OFF);   // [32][33]

    const int er = lane >> 2;
    const int ec = (lane & 3) * 2;
#pragma unroll
    for (int mt = 0; mt < 2; mt++) {
#pragma unroll
        for (int nt = 0; nt < 6; nt++) {
            const int col = wn + nt * 8 + ec;
            const int row = wm + mt * 16 + er;
            sqkv[row * 97 + col]           = acc[mt][nt][0];
            sqkv[row * 97 + col + 1]       = acc[mt][nt][1];
            sqkv[(row + 8) * 97 + col]     = acc[mt][nt][2];
            sqkv[(row + 8) * 97 + col + 1] = acc[mt][nt][3];
        }
    }
    __syncthreads();

    const unsigned FULL = 0xffffffffu;
    const int w = wid;
#pragma unroll 1
    for (int bb = 0; bb < 4; bb++) {
        const int rbase = bb * 32;
#pragma unroll
        for (int rr = 0; rr < 4; rr++) {
            const int r = w + rr * 8;
            float s = 0.0f;
#pragma unroll
            for (int e = 0; e < 32; e++)    // q row broadcast; k row stride-97 (conflict-free)
                s += sqkv[(rbase + r) * 97 + e] * sqkv[(rbase + lane) * 97 + 32 + e];
            s *= 0.17677669529663687f;       // 32^-0.5
            if (lane > r) s = -1e30f;        // causal mask

            float m = s;
#pragma unroll
            for (int off = 16; off > 0; off >>= 1)
                m = fmaxf(m, __shfl_xor_sync(FULL, m, off));
            float p = __expf(s - m);
            float sum = p;
#pragma unroll
            for (int off = 16; off > 0; off >>= 1)
                sum += __shfl_xor_sync(FULL, sum, off);
            p /= sum;

            float o = 0.0f;
#pragma unroll
            for (int ss = 0; ss < 32; ss++) {
                float ps = __shfl_sync(FULL, p, ss);
                o += ps * sqkv[(rbase + ss) * 97 + 64 + lane];   // v, stride-1 in lane
            }
            so[r * 33 + lane] = o;
        }
        __syncthreads();

        const int bglobal = blockIdx.y * 4 + bb;
        for (int idx = tid; idx < 1024; idx += 256) {
            const int d = idx >> 5, t = idx & 31;
            unsigned short hi, lo;
            split_bf16(so[t * 33 + d], hi, lo);
            const size_t of = (size_t)(bglobal * 32 + d) * EE + h * 32 + t;
            g_ohi[of] = hi;
            g_olo[of] = lo;
        }
        __syncthreads();
    }
}

// ===========================================================================
// Kernel 2: projection GEMM (unchanged R13 structure, tensor=75.1% measured).
// C cols [n0, n0+128); weights rows wrow0+n; BM=BN=128, BK=32, 3-stage.
// ===========================================================================
#define GEMM_STAGE_BYTES 32768
#define GEMM_SMEM_BYTES  (3 * GEMM_STAGE_BYTES)   // 96 KB, 2 CTAs/SM

__global__ __launch_bounds__(256, 2) void k_gemm_bf16(
    const unsigned short* __restrict__ Ahi, const unsigned short* __restrict__ Alo,
    int wrow0, const float* __restrict__ bias, float* __restrict__ C, int NTOT) {

    extern __shared__ unsigned short sm[];
    const uint32_t uSm = (uint32_t)__cvta_generic_to_shared(sm);

    const int tid  = threadIdx.x;
    const int wid  = tid >> 5;
    const int lane = tid & 31;
    const int n0   = blockIdx.x * 128;
    const int m0   = blockIdx.y * 128;
    const int wm   = (wid >> 1) * 32;
    const int wn   = (wid & 1) * 64;

    float acc[2][8][4];
#pragma unroll
    for (int mt = 0; mt < 2; mt++)
#pragma unroll
        for (int nt = 0; nt < 8; nt++)
#pragma unroll
            for (int e = 0; e < 4; e++) acc[mt][nt][e] = 0.0f;

    const int lm[2] = { tid >> 2, (tid + 256) >> 2 };
    const int lc    = tid & 3;
    const int lsof[2] = { lm[0] * 32 + (((lc ^ ((lm[0] >> 1) & 3))) << 3),
                          lm[1] * 32 + (((lc ^ ((lm[1] >> 1) & 3))) << 3) };

    const int NSTEP = EE / 32;   // 16

    auto load_stage = [&](int s, int k0) {
        const uint32_t sb = uSm + (uint32_t)s * GEMM_STAGE_BYTES;
#pragma unroll
        for (int p = 0; p < 2; p++) {
            const uint32_t so = (uint32_t)lsof[p] * 2u;
            const size_t aof = (size_t)(m0 + lm[p]) * EE + k0 + lc * 8;
            const size_t bof = (size_t)(wrow0 + n0 + lm[p]) * EE + k0 + lc * 8;
            cp16(sb +          so, Ahi   + aof);
            cp16(sb + 8192u  + so, Alo   + aof);
            cp16(sb + 16384u + so, g_whi + bof);
            cp16(sb + 24576u + so, g_wlo + bof);
        }
    };

    const int q  = lane >> 3;
    const int ri = lane & 7;

    load_stage(0, 0);  cp_commit();
    load_stage(1, 32); cp_commit();

    int cur = 0;
#pragma unroll 1
    for (int kt = 0; kt < NSTEP; kt++) {
        if (kt < NSTEP - 2) cp_wait1(); else cp_wait0();
        __syncthreads();
        if (kt + 2 < NSTEP) {
            load_stage((cur + 2) % 3, (kt + 2) * 32);
            cp_commit();
        }

        const uint32_t sb   = uSm + (uint32_t)cur * GEMM_STAGE_BYTES;
        const uint32_t bAhi = sb,          bAlo = sb + 8192u;
        const uint32_t bBhi = sb + 16384u, bBlo = sb + 24576u;

#pragma unroll
        for (int s = 0; s < 2; s++) {
            uint32_t afr[2][2][4];
#pragma unroll
            for (int mt = 0; mt < 2; mt++) {
                const int r = wm + mt * 16 + (q & 1) * 8 + ri;
                const int j = 2 * s + (q >> 1);
                const uint32_t off = (uint32_t)(r * 32 + ((j ^ ((r >> 1) & 3)) << 3)) * 2u;
                ldsm_x4(afr[mt][0], bAhi + off);
                ldsm_x4(afr[mt][1], bAlo + off);
            }
#pragma unroll
            for (int np = 0; np < 4; np++) {
                const int r = wn + np * 16 + (q >> 1) * 8 + ri;
                const int j = 2 * s + (q & 1);
                const uint32_t off = (uint32_t)(r * 32 + ((j ^ ((r >> 1) & 3)) << 3)) * 2u;
                uint32_t bh[4], bl[4];
                ldsm_x4(bh, bBhi + off);
                ldsm_x4(bl, bBlo + off);
#pragma unroll
                for (int mt = 0; mt < 2; mt++) {
                    float* d0 = acc[mt][2 * np];
                    float* d1 = acc[mt][2 * np + 1];
                    mma16816(d0, afr[mt][0], bh[0], bh[1]);
                    mma16816(d0, afr[mt][0], bl[0], bl[1]);
                    mma16816(d0, afr[mt][1], bh[0], bh[1]);
                    mma16816(d1, afr[mt][0], bh[2], bh[3]);
                    mma16816(d1, afr[mt][0], bl[2], bl[3]);
                    mma16816(d1, afr[mt][1], bh[2], bh[3]);
                }
            }
        }
        cur = (cur + 1) % 3;
    }

    const int er = lane >> 2;
    const int ec = (lane & 3) * 2;
#pragma unroll
    for (int mt = 0; mt < 2; mt++) {
#pragma unroll
        for (int nt = 0; nt < 8; nt++) {
            const int col = n0 + wn + nt * 8 + ec;
            float b0 = 0.0f, b1 = 0.0f;
            if (bias) { b0 = bias[col]; b1 = bias[col + 1]; }
            const int row = m0 + wm + mt * 16 + er;
            __stcs((float2*)(C + (size_t)row * NTOT + col),
                   make_float2(acc[mt][nt][0] + b0, acc[mt][nt][1] + b1));
            __stcs((float2*)(C + (size_t)(row + 8) * NTOT + col),
                   make_float2(acc[mt][nt][2] + b0, acc[mt][nt][3] + b1));
        }
    }
}

// ---------------------------------------------------------------------------
// Launch.  Inputs: 0=x 1=Wq 2=Wk 3=Wv 4=Wp 5=bp ; output fp32 [B, 32, 512]
// Sequence: 0 conv | 1 fused qkv+attn | 2 proj   (repeats; capture index 5
// in the replay cycle lands on the proj GEMM)
// ---------------------------------------------------------------------------
extern "C" void kernel_launch(void* const* d_in, const int* in_sizes, int n_in,
                              void* d_out, int out_size) {
    (void)in_sizes; (void)n_in; (void)out_size;
    const float* x  = (const float*)d_in[0];
    const float* Wq = (const float*)d_in[1];
    const float* Wk = (const float*)d_in[2];
    const float* Wv = (const float*)d_in[3];
    const float* Wp = (const float*)d_in[4];
    const float* bp = (const float*)d_in[5];
    float* out = (float*)d_out;

    void *p_xhi, *p_xlo, *p_ohi, *p_olo;
    cudaGetSymbolAddress(&p_xhi, g_xhi);
    cudaGetSymbolAddress(&p_xlo, g_xlo);
    cudaGetSymbolAddress(&p_ohi, g_ohi);
    cudaGetSymbolAddress(&p_olo, g_olo);

    cudaFuncSetAttribute(k_qkv_attn, cudaFuncAttributeMaxDynamicSharedMemorySize,
                         FQ_SMEM_BYTES);
    cudaFuncSetAttribute(k_gemm_bf16, cudaFuncAttributeMaxDynamicSharedMemorySize,
                         GEMM_SMEM_BYTES);

    // 1) split x + weights to bf16 hi+lo
    k_conv<<<CONV_X_BLOCKS + CONV_W_BLOCKS, 256>>>(x, Wq, Wk, Wv, Wp);

    // 2) fused QKV-GEMM + attention: grid (heads, m-blocks)
    dim3 gf(HH, MROWS / 128);                                 // (16, 1024)
    k_qkv_attn<<<gf, 256, FQ_SMEM_BYTES>>>(
        (const unsigned short*)p_xhi, (const unsigned short*)p_xlo);

    // 3) proj: [131072 x 512] + bias
    dim3 g3(EE / 128, MROWS / 128);                           // (4, 1024)
    k_gemm_bf16<<<g3, 256, GEMM_SMEM_BYTES>>>(
        (const unsigned short*)p_ohi, (const unsigned short*)p_olo,
        1536, bp, out, EE);
}